// round 3
// baseline (speedup 1.0000x reference)
#include <cuda_runtime.h>
#include <cuda_bf16.h>

// ---------------------------------------------------------------------------
// OT (Sinkhorn) attention, B=8, N=1024, D=64, fp32.
// Scaling-form Sinkhorn: S = exp(-(1-QK^T)/eps) stored bf16 (L2-resident),
// a = mu/(S w); w = mu/(S^T a), 100 iters (cluster-early-break),
// out = a (.) (S (w (.) V)) + V.
// One 8-CTA cluster per batch; barrier.cluster for per-iteration sync.
// ---------------------------------------------------------------------------

#define BATCH 8
#define NSEQ  1024
#define DIM   64
#define EPS_F 0.05f
#define MU_F  (1.0f/1024.0f + 1e-8f)

// scratch (__device__ globals: allocation-free)
__device__ __nv_bfloat16 g_S[(size_t)BATCH * NSEQ * NSEQ];   // 16 MB
__device__ float g_Qn[BATCH * NSEQ * DIM];
__device__ float g_Kn[BATCH * NSEQ * DIM];
__device__ float g_a[BATCH * NSEQ];
__device__ float g_w[BATCH * NSEQ];

// ---------------- helpers ----------------
__device__ __forceinline__ float bflo(unsigned x) { return __uint_as_float(x << 16); }
__device__ __forceinline__ float bfhi(unsigned x) { return __uint_as_float(x & 0xFFFF0000u); }

__device__ __forceinline__ unsigned pk2(float a, float b) {
    __nv_bfloat162 t = __floats2bfloat162_rn(a, b);  // .x = a (low)
    return *reinterpret_cast<unsigned*>(&t);
}

__device__ __forceinline__ unsigned smem_u32(const void* p) {
    unsigned a;
    asm("{ .reg .u64 t; cvta.to.shared.u64 t, %1; cvt.u32.u64 %0, t; }" : "=r"(a) : "l"(p));
    return a;
}
__device__ __forceinline__ unsigned cluster_rank() {
    unsigned r; asm("mov.u32 %0, %%cluster_ctarank;" : "=r"(r)); return r;
}
__device__ __forceinline__ unsigned mapa_u32(unsigned addr, unsigned rank) {
    unsigned r; asm("mapa.shared::cluster.u32 %0, %1, %2;" : "=r"(r) : "r"(addr), "r"(rank));
    return r;
}
__device__ __forceinline__ float ld_dsmem_f32(unsigned addr) {
    float v; asm volatile("ld.shared::cluster.f32 %0, [%1];" : "=f"(v) : "r"(addr)); return v;
}
__device__ __forceinline__ void st_dsmem_f32(unsigned addr, float v) {
    asm volatile("st.shared::cluster.f32 [%0], %1;" :: "r"(addr), "f"(v));
}
#define CLUSTER_SYNC() do { \
    asm volatile("barrier.cluster.arrive.aligned;" ::: "memory"); \
    asm volatile("barrier.cluster.wait.aligned;"   ::: "memory"); \
} while (0)

// ---------------- kernel 1: L2-normalize rows of q,k ----------------
__global__ void __launch_bounds__(256) norm_kernel(const float* __restrict__ q,
                                                   const float* __restrict__ k) {
    int gw   = (blockIdx.x * 256 + threadIdx.x) >> 5;   // global warp = row id (0..16383)
    int lane = threadIdx.x & 31;
    const float* src;
    float* dst;
    if (gw < BATCH * NSEQ) { src = q + (size_t)gw * DIM;                dst = g_Qn + (size_t)gw * DIM; }
    else                   { src = k + (size_t)(gw - BATCH*NSEQ) * DIM; dst = g_Kn + (size_t)(gw - BATCH*NSEQ) * DIM; }
    float2 v = reinterpret_cast<const float2*>(src)[lane];
    float s = v.x * v.x + v.y * v.y;
    #pragma unroll
    for (int o = 16; o > 0; o >>= 1) s += __shfl_xor_sync(~0u, s, o);
    float n   = sqrtf(s);
    float inv = 1.0f / fmaxf(n, 1e-12f);
    reinterpret_cast<float2*>(dst)[lane] = make_float2(v.x * inv, v.y * inv);
}

// ---------------- kernel 2: S = exp((QK^T - 1)/eps), bf16 ----------------
// grid (32, 8): 32 row-blocks of 32 rows x batch. 256 threads.
__global__ void __launch_bounds__(256) gemmS_kernel() {
    int b  = blockIdx.y;
    int i0 = blockIdx.x * 32;
    __shared__ __align__(16) float Qs[32][DIM];
    __shared__ __align__(16) float Ks[128][DIM];

    const float* Qp = g_Qn + (size_t)(b * NSEQ + i0) * DIM;
    for (int t = threadIdx.x; t < 32 * DIM / 4; t += 256)
        reinterpret_cast<float4*>(&Qs[0][0])[t] = reinterpret_cast<const float4*>(Qp)[t];

    int ti = threadIdx.x >> 5;   // 0..7 -> rows 4ti..4ti+3
    int tj = threadIdx.x & 31;   // cols 4tj..4tj+3

    for (int jt = 0; jt < NSEQ; jt += 128) {
        __syncthreads();
        const float* Kp = g_Kn + (size_t)(b * NSEQ + jt) * DIM;
        for (int t = threadIdx.x; t < 128 * DIM / 4; t += 256)
            reinterpret_cast<float4*>(&Ks[0][0])[t] = reinterpret_cast<const float4*>(Kp)[t];
        __syncthreads();

        float acc[4][4];
        #pragma unroll
        for (int r = 0; r < 4; ++r)
            #pragma unroll
            for (int c = 0; c < 4; ++c) acc[r][c] = 0.f;

        #pragma unroll
        for (int d = 0; d < DIM; d += 4) {
            float4 qv[4], kv[4];
            #pragma unroll
            for (int r = 0; r < 4; ++r) qv[r] = *reinterpret_cast<const float4*>(&Qs[4*ti + r][d]);
            #pragma unroll
            for (int c = 0; c < 4; ++c) kv[c] = *reinterpret_cast<const float4*>(&Ks[4*tj + c][d]);
            #pragma unroll
            for (int r = 0; r < 4; ++r)
                #pragma unroll
                for (int c = 0; c < 4; ++c) {
                    acc[r][c] = fmaf(qv[r].x, kv[c].x, acc[r][c]);
                    acc[r][c] = fmaf(qv[r].y, kv[c].y, acc[r][c]);
                    acc[r][c] = fmaf(qv[r].z, kv[c].z, acc[r][c]);
                    acc[r][c] = fmaf(qv[r].w, kv[c].w, acc[r][c]);
                }
        }

        #pragma unroll
        for (int r = 0; r < 4; ++r) {
            size_t rowi = (size_t)(b * NSEQ + i0 + 4*ti + r);
            float e0 = __expf(20.0f * (acc[r][0] - 1.0f));
            float e1 = __expf(20.0f * (acc[r][1] - 1.0f));
            float e2 = __expf(20.0f * (acc[r][2] - 1.0f));
            float e3 = __expf(20.0f * (acc[r][3] - 1.0f));
            uint2 p = make_uint2(pk2(e0, e1), pk2(e2, e3));
            *reinterpret_cast<uint2*>(g_S + (rowi << 10) + jt + 4*tj) = p;
        }
    }
}

// ---------------- kernel 3: Sinkhorn loop ----------------
// grid 64 CTAs = 8 clusters of 8 (one cluster per batch), 512 threads.
// CTA owns 128 rows of its batch's S.
__global__ void __cluster_dims__(8, 1, 1) __launch_bounds__(512) sink_kernel() {
    __shared__ __align__(16) float sw[NSEQ];    // full w for this batch
    __shared__ __align__(16) float sa[128];     // my a slice
    __shared__ __align__(16) float spc[NSEQ];   // my partial c
    __shared__ float swErr[16];
    __shared__ float sErrTot;
    __shared__ int   sBreak;

    unsigned rank = cluster_rank();       // 0..7
    int b    = blockIdx.x >> 3;
    int tid  = threadIdx.x;
    int wid  = tid >> 5;
    int lane = tid & 31;

    for (int t = tid; t < NSEQ; t += 512) sw[t] = 1.0f;
    if (tid < 128) sa[tid] = 1.0f;
    if (tid == 0) sBreak = 0;
    __syncthreads();

    const __nv_bfloat16* Sbase = g_S + ((size_t)(b * NSEQ + rank * 128) << 10);

    unsigned spc_u32  = smem_u32(spc);
    unsigned sw_u32   = smem_u32(sw);
    unsigned err_u32  = smem_u32(&sErrTot);

    #pragma unroll 1
    for (int iter = 0; iter < 100; ++iter) {
        // -------- preload w into registers: lane covers cols {256c + 8*lane + k}
        float wr[4][8];
        #pragma unroll
        for (int c = 0; c < 4; ++c) {
            float4 w0 = *reinterpret_cast<const float4*>(&sw[c*256 + lane*8]);
            float4 w1 = *reinterpret_cast<const float4*>(&sw[c*256 + lane*8 + 4]);
            wr[c][0] = w0.x; wr[c][1] = w0.y; wr[c][2] = w0.z; wr[c][3] = w0.w;
            wr[c][4] = w1.x; wr[c][5] = w1.y; wr[c][6] = w1.z; wr[c][7] = w1.w;
        }

        // -------- pass 1: r_i = sum_j s_ij w_j ; a_i = mu / r_i
        float errAcc = 0.f;
        #pragma unroll 1
        for (int r8 = 0; r8 < 8; ++r8) {
            int row = wid * 8 + r8;
            const uint4* p = reinterpret_cast<const uint4*>(Sbase + ((size_t)row << 10));
            float a0 = 0.f, a1 = 0.f, a2 = 0.f, a3 = 0.f;
            #pragma unroll
            for (int c = 0; c < 4; ++c) {
                uint4 v = p[c*32 + lane];
                a0 = fmaf(bflo(v.x), wr[c][0], a0); a1 = fmaf(bfhi(v.x), wr[c][1], a1);
                a2 = fmaf(bflo(v.y), wr[c][2], a2); a3 = fmaf(bfhi(v.y), wr[c][3], a3);
                a0 = fmaf(bflo(v.z), wr[c][4], a0); a1 = fmaf(bfhi(v.z), wr[c][5], a1);
                a2 = fmaf(bflo(v.w), wr[c][6], a2); a3 = fmaf(bfhi(v.w), wr[c][7], a3);
            }
            float acc = (a0 + a1) + (a2 + a3);
            #pragma unroll
            for (int o = 16; o > 0; o >>= 1) acc += __shfl_xor_sync(~0u, acc, o);
            if (lane == 0) {
                float aold = sa[row];
                float anew = MU_F / acc;
                sa[row] = anew;
                errAcc += fabsf(EPS_F * (__logf(anew) - __logf(aold)));
            }
        }
        if (lane == 0) swErr[wid] = errAcc;
        __syncthreads();
        if (tid == 0) {
            float e = 0.f;
            #pragma unroll
            for (int t2 = 0; t2 < 16; ++t2) e += swErr[t2];
            sErrTot = e;
        }

        // -------- pass 2: partial c_j = sum_{i in mine} s_ij a_i (warp owns 64 cols)
        {
            float cc[8];
            #pragma unroll
            for (int t2 = 0; t2 < 8; ++t2) cc[t2] = 0.f;
            int sub = lane >> 3;     // row residue 0..3
            int l8  = lane & 7;      // col octet
            const __nv_bfloat16* base2 = Sbase + wid*64 + l8*8;
            #pragma unroll 1
            for (int st = 0; st < 32; ++st) {
                int row = st*4 + sub;
                uint4 v = *reinterpret_cast<const uint4*>(base2 + ((size_t)row << 10));
                float a = sa[row];
                cc[0] = fmaf(bflo(v.x), a, cc[0]); cc[1] = fmaf(bfhi(v.x), a, cc[1]);
                cc[2] = fmaf(bflo(v.y), a, cc[2]); cc[3] = fmaf(bfhi(v.y), a, cc[3]);
                cc[4] = fmaf(bflo(v.z), a, cc[4]); cc[5] = fmaf(bfhi(v.z), a, cc[5]);
                cc[6] = fmaf(bflo(v.w), a, cc[6]); cc[7] = fmaf(bfhi(v.w), a, cc[7]);
            }
            #pragma unroll
            for (int t2 = 0; t2 < 8; ++t2) {
                cc[t2] += __shfl_xor_sync(~0u, cc[t2], 8);
                cc[t2] += __shfl_xor_sync(~0u, cc[t2], 16);
            }
            if (sub == 0) {
                float4* dst = reinterpret_cast<float4*>(&spc[wid*64 + l8*8]);
                dst[0] = make_float4(cc[0], cc[1], cc[2], cc[3]);
                dst[1] = make_float4(cc[4], cc[5], cc[6], cc[7]);
            }
        }
        __syncthreads();
        CLUSTER_SYNC();   // all spc / sErrTot visible cluster-wide

        // -------- reduce c slice (rank owns cols [128*rank, +128)), compute & broadcast w
        if (tid < 128) {
            int col = rank * 128 + tid;
            float cs = 0.f;
            #pragma unroll
            for (unsigned r2 = 0; r2 < 8; ++r2)
                cs += ld_dsmem_f32(mapa_u32(spc_u32 + 4u*col, r2));
            float wnew = MU_F / cs;
            #pragma unroll
            for (unsigned r2 = 0; r2 < 8; ++r2)
                st_dsmem_f32(mapa_u32(sw_u32 + 4u*col, r2), wnew);
        } else if (tid == 128) {
            float e = 0.f;
            #pragma unroll
            for (unsigned r2 = 0; r2 < 8; ++r2)
                e += ld_dsmem_f32(mapa_u32(err_u32, r2));
            // batch mean < THRESH/8  <=>  sum < 1024 * 1e-6/8
            sBreak = (e < 1.28e-4f) ? 1 : 0;
        }
        CLUSTER_SYNC();   // w broadcast complete; sBreak ready (CTA-local, synced)
        if (sBreak) break;
    }

    if (tid < 128) {
        g_a[b * NSEQ + rank * 128 + tid] = sa[tid];
        g_w[b * NSEQ + rank * 128 + tid] = sw[rank * 128 + tid];
    }
}

// ---------------- kernel 4: out = a (.) (S (w (.) V)) + V ----------------
// grid (32, 8): 32-row blocks x batch, 256 threads (8 warps = d-groups).
__global__ void __launch_bounds__(256) out_kernel(const float* __restrict__ V,
                                                  float* __restrict__ out) {
    int b  = blockIdx.y;
    int i0 = blockIdx.x * 32;
    __shared__ __align__(16) float Yt[128][DIM];          // (w .* V) tile, 32 KB
    __shared__ __align__(16) unsigned short Ssm[128][32]; // S^T tile, 8 KB
    __shared__ float wt[128];

    int tid  = threadIdx.x;
    int wid  = tid >> 5;    // d-group: d = 8*wid .. +8
    int lane = tid & 31;    // row within block

    float acc[8];
    #pragma unroll
    for (int t = 0; t < 8; ++t) acc[t] = 0.f;

    const float* Vb = V + (size_t)b * NSEQ * DIM;

    for (int jt = 0; jt < NSEQ; jt += 128) {
        __syncthreads();
        if (tid < 128) wt[tid] = g_w[b * NSEQ + jt + tid];
        __syncthreads();
        // Yt[j][d] = w[jt+j] * V[b][jt+j][d]
        for (int t = tid; t < 2048; t += 256) {
            int j = t >> 4, dq = t & 15;
            float4 v4 = reinterpret_cast<const float4*>(Vb + (size_t)(jt + j) * DIM)[dq];
            float wv = wt[j];
            *reinterpret_cast<float4*>(&Yt[j][dq*4]) =
                make_float4(v4.x*wv, v4.y*wv, v4.z*wv, v4.w*wv);
        }
        // S^T tile: Ssm[j][r] = S[b][i0+r][jt+j]
        const __nv_bfloat16* Sb2 = g_S + ((size_t)(b * NSEQ + i0) << 10) + jt;
        for (int t = tid; t < 512; t += 256) {
            int r = t >> 4, jq = t & 15;
            uint4 v = *reinterpret_cast<const uint4*>(Sb2 + ((size_t)r << 10) + jq*8);
            Ssm[jq*8 + 0][r] = (unsigned short)(v.x);
            Ssm[jq*8 + 1][r] = (unsigned short)(v.x >> 16);
            Ssm[jq*8 + 2][r] = (unsigned short)(v.y);
            Ssm[jq*8 + 3][r] = (unsigned short)(v.y >> 16);
            Ssm[jq*8 + 4][r] = (unsigned short)(v.z);
            Ssm[jq*8 + 5][r] = (unsigned short)(v.z >> 16);
            Ssm[jq*8 + 6][r] = (unsigned short)(v.w);
            Ssm[jq*8 + 7][r] = (unsigned short)(v.w >> 16);
        }
        __syncthreads();

        #pragma unroll 4
        for (int j = 0; j < 128; ++j) {
            float s = __uint_as_float(((unsigned)Ssm[j][lane]) << 16);
            float4 y0 = *reinterpret_cast<const float4*>(&Yt[j][wid*8]);
            float4 y1 = *reinterpret_cast<const float4*>(&Yt[j][wid*8 + 4]);
            acc[0] = fmaf(s, y0.x, acc[0]); acc[1] = fmaf(s, y0.y, acc[1]);
            acc[2] = fmaf(s, y0.z, acc[2]); acc[3] = fmaf(s, y0.w, acc[3]);
            acc[4] = fmaf(s, y1.x, acc[4]); acc[5] = fmaf(s, y1.y, acc[5]);
            acc[6] = fmaf(s, y1.z, acc[6]); acc[7] = fmaf(s, y1.w, acc[7]);
        }
    }

    int row = i0 + lane;
    float a = g_a[b * NSEQ + row];
    const float* vp = Vb + (size_t)row * DIM + wid * 8;
    float* op = out + ((size_t)b * NSEQ + row) * DIM + wid * 8;
    #pragma unroll
    for (int t = 0; t < 8; ++t) op[t] = fmaf(acc[t], a, vp[t]);
}

// ---------------- launcher ----------------
extern "C" void kernel_launch(void* const* d_in, const int* in_sizes, int n_in,
                              void* d_out, int out_size) {
    const float* q = (const float*)d_in[0];
    const float* k = (const float*)d_in[1];
    const float* V = (const float*)d_in[2];
    float* out = (float*)d_out;
    (void)in_sizes; (void)n_in; (void)out_size;

    norm_kernel<<<2048, 256>>>(q, k);
    gemmS_kernel<<<dim3(32, 8), 256>>>();
    sink_kernel<<<64, 512>>>();
    out_kernel<<<dim3(32, 8), 256>>>(V, out);
}

// round 6
// speedup vs baseline: 1.3674x; 1.3674x over previous
#include <cuda_runtime.h>
#include <cuda_bf16.h>

// ---------------------------------------------------------------------------
// OT (Sinkhorn) attention, B=8, N=1024, D=64, fp32.
// Scaling-form Sinkhorn with FUSED passes: stream each row of S once per
// iteration; dot with w -> a_new -> rank-1 update into column accumulators.
// One cluster per batch (16 CTAs if HW allows, else 8). bf16 S, L2-resident.
// ---------------------------------------------------------------------------

#define BATCH 8
#define NSEQ  1024
#define DIM   64
#define EPS_F 0.05f
#define MU_F  (1.0f/1024.0f + 1e-8f)

__device__ __nv_bfloat16 g_S[(size_t)BATCH * NSEQ * NSEQ];   // 16 MB
__device__ float g_Qn[BATCH * NSEQ * DIM];
__device__ float g_Kn[BATCH * NSEQ * DIM];
__device__ float g_a[BATCH * NSEQ];
__device__ float g_w[BATCH * NSEQ];

// ---------------- helpers ----------------
__device__ __forceinline__ float bflo(unsigned x) { return __uint_as_float(x << 16); }
__device__ __forceinline__ float bfhi(unsigned x) { return __uint_as_float(x & 0xFFFF0000u); }

__device__ __forceinline__ unsigned pk2(float a, float b) {
    __nv_bfloat162 t = __floats2bfloat162_rn(a, b);  // .x = a (low)
    return *reinterpret_cast<unsigned*>(&t);
}

__device__ __forceinline__ unsigned smem_u32(const void* p) {
    unsigned a;
    asm("{ .reg .u64 t; cvta.to.shared.u64 t, %1; cvt.u32.u64 %0, t; }" : "=r"(a) : "l"(p));
    return a;
}
__device__ __forceinline__ unsigned cluster_rank() {
    unsigned r; asm("mov.u32 %0, %%cluster_ctarank;" : "=r"(r)); return r;
}
__device__ __forceinline__ unsigned cluster_nctas() {
    unsigned r; asm("mov.u32 %0, %%cluster_nctaid.x;" : "=r"(r)); return r;
}
__device__ __forceinline__ unsigned mapa_u32(unsigned addr, unsigned rank) {
    unsigned r; asm("mapa.shared::cluster.u32 %0, %1, %2;" : "=r"(r) : "r"(addr), "r"(rank));
    return r;
}
__device__ __forceinline__ float ld_dsmem_f32(unsigned addr) {
    float v; asm volatile("ld.shared::cluster.f32 %0, [%1];" : "=f"(v) : "r"(addr)); return v;
}
__device__ __forceinline__ void st_dsmem_f32(unsigned addr, float v) {
    asm volatile("st.shared::cluster.f32 [%0], %1;" :: "r"(addr), "f"(v));
}
#define CLUSTER_SYNC() do { \
    asm volatile("barrier.cluster.arrive.aligned;" ::: "memory"); \
    asm volatile("barrier.cluster.wait.aligned;"   ::: "memory"); \
} while (0)

// ---------------- kernel 1: L2-normalize rows of q,k ----------------
__global__ void __launch_bounds__(256) norm_kernel(const float* __restrict__ q,
                                                   const float* __restrict__ k) {
    int gw   = (blockIdx.x * 256 + threadIdx.x) >> 5;
    int lane = threadIdx.x & 31;
    const float* src;
    float* dst;
    if (gw < BATCH * NSEQ) { src = q + (size_t)gw * DIM;                dst = g_Qn + (size_t)gw * DIM; }
    else                   { src = k + (size_t)(gw - BATCH*NSEQ) * DIM; dst = g_Kn + (size_t)(gw - BATCH*NSEQ) * DIM; }
    float2 v = reinterpret_cast<const float2*>(src)[lane];
    float s = v.x * v.x + v.y * v.y;
    #pragma unroll
    for (int o = 16; o > 0; o >>= 1) s += __shfl_xor_sync(~0u, s, o);
    float n   = sqrtf(s);
    float inv = 1.0f / fmaxf(n, 1e-12f);
    reinterpret_cast<float2*>(dst)[lane] = make_float2(v.x * inv, v.y * inv);
}

// ---------------- kernel 2: S = exp((QK^T - 1)/eps), bf16 ----------------
__global__ void __launch_bounds__(256) gemmS_kernel() {
    int b  = blockIdx.y;
    int i0 = blockIdx.x * 32;
    __shared__ __align__(16) float Qs[32][DIM];
    __shared__ __align__(16) float Ks[128][DIM];

    const float* Qp = g_Qn + (size_t)(b * NSEQ + i0) * DIM;
    for (int t = threadIdx.x; t < 32 * DIM / 4; t += 256)
        reinterpret_cast<float4*>(&Qs[0][0])[t] = reinterpret_cast<const float4*>(Qp)[t];

    int ti = threadIdx.x >> 5;
    int tj = threadIdx.x & 31;

    for (int jt = 0; jt < NSEQ; jt += 128) {
        __syncthreads();
        const float* Kp = g_Kn + (size_t)(b * NSEQ + jt) * DIM;
        for (int t = threadIdx.x; t < 128 * DIM / 4; t += 256)
            reinterpret_cast<float4*>(&Ks[0][0])[t] = reinterpret_cast<const float4*>(Kp)[t];
        __syncthreads();

        float acc[4][4];
        #pragma unroll
        for (int r = 0; r < 4; ++r)
            #pragma unroll
            for (int c = 0; c < 4; ++c) acc[r][c] = 0.f;

        #pragma unroll
        for (int d = 0; d < DIM; d += 4) {
            float4 qv[4], kv[4];
            #pragma unroll
            for (int r = 0; r < 4; ++r) qv[r] = *reinterpret_cast<const float4*>(&Qs[4*ti + r][d]);
            #pragma unroll
            for (int c = 0; c < 4; ++c) kv[c] = *reinterpret_cast<const float4*>(&Ks[4*tj + c][d]);
            #pragma unroll
            for (int r = 0; r < 4; ++r)
                #pragma unroll
                for (int c = 0; c < 4; ++c) {
                    acc[r][c] = fmaf(qv[r].x, kv[c].x, acc[r][c]);
                    acc[r][c] = fmaf(qv[r].y, kv[c].y, acc[r][c]);
                    acc[r][c] = fmaf(qv[r].z, kv[c].z, acc[r][c]);
                    acc[r][c] = fmaf(qv[r].w, kv[c].w, acc[r][c]);
                }
        }

        #pragma unroll
        for (int r = 0; r < 4; ++r) {
            size_t rowi = (size_t)(b * NSEQ + i0 + 4*ti + r);
            float e0 = __expf(20.0f * (acc[r][0] - 1.0f));
            float e1 = __expf(20.0f * (acc[r][1] - 1.0f));
            float e2 = __expf(20.0f * (acc[r][2] - 1.0f));
            float e3 = __expf(20.0f * (acc[r][3] - 1.0f));
            uint2 p = make_uint2(pk2(e0, e1), pk2(e2, e3));
            *reinterpret_cast<uint2*>(g_S + (rowi << 10) + jt + 4*tj) = p;
        }
    }
}

// ---------------- kernel 3: fused Sinkhorn loop ----------------
// grid = BATCH * csz CTAs, one csz-CTA cluster per batch, 512 threads.
// Each CTA owns NSEQ/csz rows; warp owns rowsPerCta/16 rows.
// Per iteration, each S row is read ONCE: dot with w -> a_new -> rank-1 into
// per-lane column accumulators (lane covers cols {c*256 + lane*8 + e}).
__global__ void __launch_bounds__(512) sink_kernel() {
    __shared__ __align__(16) float sw[NSEQ];        // 4 KB  full w (batch)
    __shared__ __align__(16) float sa[128];         // my a slice
    __shared__ __align__(16) float spc[NSEQ];       // 4 KB  CTA-partial c
    __shared__ __align__(16) float redbuf[8][NSEQ]; // 32 KB warp-tree buffer
    __shared__ float swErr[16];
    __shared__ float sErrTot;
    __shared__ int   sBreak;

    unsigned csz  = cluster_nctas();          // 8 or 16
    unsigned rank = cluster_rank();
    int b           = blockIdx.x / (int)csz;
    int rowsPerCta  = NSEQ / (int)csz;        // 128 or 64
    int rowsPerWarp = rowsPerCta >> 4;        // 8 or 4
    int colsPerCta  = NSEQ / (int)csz;
    int tid  = threadIdx.x;
    int wid  = tid >> 5;
    int lane = tid & 31;

    for (int t = tid; t < NSEQ; t += 512) sw[t] = 1.0f;
    if (tid < rowsPerCta) sa[tid] = 1.0f;
    if (tid == 0) sBreak = 0;
    __syncthreads();

    const __nv_bfloat16* Sbase = g_S + ((size_t)(b * NSEQ + (int)rank * rowsPerCta) << 10);

    unsigned spc_u32 = smem_u32(spc);
    unsigned sw_u32  = smem_u32(sw);
    unsigned err_u32 = smem_u32(&sErrTot);

    #pragma unroll 1
    for (int iter = 0; iter < 100; ++iter) {
        // preload w: lane covers cols {c*256 + lane*8 + e}
        float wr[4][8];
        #pragma unroll
        for (int c = 0; c < 4; ++c) {
            float4 w0 = *reinterpret_cast<const float4*>(&sw[c*256 + lane*8]);
            float4 w1 = *reinterpret_cast<const float4*>(&sw[c*256 + lane*8 + 4]);
            wr[c][0] = w0.x; wr[c][1] = w0.y; wr[c][2] = w0.z; wr[c][3] = w0.w;
            wr[c][4] = w1.x; wr[c][5] = w1.y; wr[c][6] = w1.z; wr[c][7] = w1.w;
        }

        float cc[4][8];
        #pragma unroll
        for (int c = 0; c < 4; ++c)
            #pragma unroll
            for (int e = 0; e < 8; ++e) cc[c][e] = 0.f;

        float errAcc = 0.f;

        // ---- fused pass: per row, dot -> a_new -> rank-1
        #pragma unroll 1
        for (int r8 = 0; r8 < rowsPerWarp; ++r8) {
            int row = wid * rowsPerWarp + r8;
            const uint4* p = reinterpret_cast<const uint4*>(Sbase + ((size_t)row << 10));
            uint4 v[4];
            #pragma unroll
            for (int c = 0; c < 4; ++c) v[c] = p[c*32 + lane];

            float a0 = 0.f, a1 = 0.f, a2 = 0.f, a3 = 0.f;
            #pragma unroll
            for (int c = 0; c < 4; ++c) {
                a0 = fmaf(bflo(v[c].x), wr[c][0], a0); a1 = fmaf(bfhi(v[c].x), wr[c][1], a1);
                a2 = fmaf(bflo(v[c].y), wr[c][2], a2); a3 = fmaf(bfhi(v[c].y), wr[c][3], a3);
                a0 = fmaf(bflo(v[c].z), wr[c][4], a0); a1 = fmaf(bfhi(v[c].z), wr[c][5], a1);
                a2 = fmaf(bflo(v[c].w), wr[c][6], a2); a3 = fmaf(bfhi(v[c].w), wr[c][7], a3);
            }
            float acc = (a0 + a1) + (a2 + a3);
            #pragma unroll
            for (int o = 16; o > 0; o >>= 1) acc += __shfl_xor_sync(~0u, acc, o);

            float anew = MU_F / acc;   // all lanes
            if (lane == 0) {
                float aold = sa[row];
                sa[row] = anew;
                errAcc += fabsf(EPS_F * (__logf(anew) - __logf(aold)));
            }
            // rank-1: cc_j += s_ij * a_new
            #pragma unroll
            for (int c = 0; c < 4; ++c) {
                cc[c][0] = fmaf(bflo(v[c].x), anew, cc[c][0]);
                cc[c][1] = fmaf(bfhi(v[c].x), anew, cc[c][1]);
                cc[c][2] = fmaf(bflo(v[c].y), anew, cc[c][2]);
                cc[c][3] = fmaf(bfhi(v[c].y), anew, cc[c][3]);
                cc[c][4] = fmaf(bflo(v[c].z), anew, cc[c][4]);
                cc[c][5] = fmaf(bfhi(v[c].z), anew, cc[c][5]);
                cc[c][6] = fmaf(bflo(v[c].w), anew, cc[c][6]);
                cc[c][7] = fmaf(bfhi(v[c].w), anew, cc[c][7]);
            }
        }
        if (lane == 0) swErr[wid] = errAcc;

        // ---- warp tree: 16 -> 1 column-accumulator reduction
        #pragma unroll
        for (int h = 8; h >= 1; h >>= 1) {
            if (wid >= h && wid < 2*h) {
                #pragma unroll
                for (int c = 0; c < 4; ++c) {
                    float* dst = &redbuf[wid - h][c*256 + lane*8];
                    *reinterpret_cast<float4*>(dst)     = make_float4(cc[c][0], cc[c][1], cc[c][2], cc[c][3]);
                    *reinterpret_cast<float4*>(dst + 4) = make_float4(cc[c][4], cc[c][5], cc[c][6], cc[c][7]);
                }
            }
            __syncthreads();
            if (wid < h) {
                #pragma unroll
                for (int c = 0; c < 4; ++c) {
                    const float* src = &redbuf[wid][c*256 + lane*8];
                    float4 s0 = *reinterpret_cast<const float4*>(src);
                    float4 s1 = *reinterpret_cast<const float4*>(src + 4);
                    cc[c][0] += s0.x; cc[c][1] += s0.y; cc[c][2] += s0.z; cc[c][3] += s0.w;
                    cc[c][4] += s1.x; cc[c][5] += s1.y; cc[c][6] += s1.z; cc[c][7] += s1.w;
                }
            }
            __syncthreads();
        }
        if (wid == 0) {
            #pragma unroll
            for (int c = 0; c < 4; ++c) {
                float* dst = &spc[c*256 + lane*8];
                *reinterpret_cast<float4*>(dst)     = make_float4(cc[c][0], cc[c][1], cc[c][2], cc[c][3]);
                *reinterpret_cast<float4*>(dst + 4) = make_float4(cc[c][4], cc[c][5], cc[c][6], cc[c][7]);
            }
        }
        if (tid == 0) {
            float e = 0.f;
            #pragma unroll
            for (int t2 = 0; t2 < 16; ++t2) e += swErr[t2];
            sErrTot = e;
        }
        __syncthreads();
        CLUSTER_SYNC();   // spc / sErrTot visible cluster-wide

        // ---- cross-CTA column reduce + w broadcast (rank owns colsPerCta cols)
        if (tid < colsPerCta) {
            int col = (int)rank * colsPerCta + tid;
            float cs = 0.f;
            for (unsigned r2 = 0; r2 < csz; ++r2)
                cs += ld_dsmem_f32(mapa_u32(spc_u32 + 4u*col, r2));
            float wnew = MU_F / cs;
            for (unsigned r2 = 0; r2 < csz; ++r2)
                st_dsmem_f32(mapa_u32(sw_u32 + 4u*col, r2), wnew);
        } else if (tid == colsPerCta) {
            float e = 0.f;
            for (unsigned r2 = 0; r2 < csz; ++r2)
                e += ld_dsmem_f32(mapa_u32(err_u32, r2));
            sBreak = (e < 1.28e-4f) ? 1 : 0;   // stricter than ref's global break
        }
        CLUSTER_SYNC();
        if (sBreak) break;
    }

    if (tid < rowsPerCta)
        g_a[b * NSEQ + (int)rank * rowsPerCta + tid] = sa[tid];
    if (tid < colsPerCta)
        g_w[b * NSEQ + (int)rank * colsPerCta + tid] = sw[(int)rank * colsPerCta + tid];
}

// ---------------- kernel 4: out = a (.) (S (w (.) V)) + V ----------------
// grid (32, 8), 256 threads. S^T tile staged as fp32 with pad-33 stride
// (conflict-free inner loads, <=4-way staging stores). Ssm in dynamic smem.
__global__ void __launch_bounds__(256) out_kernel(const float* __restrict__ V,
                                                  float* __restrict__ out) {
    int b  = blockIdx.y;
    int i0 = blockIdx.x * 32;
    __shared__ __align__(16) float Yt[128][DIM];   // 32 KB
    __shared__ float wt[128];
    extern __shared__ float Ssm[];                 // [128][33] fp32, 16.9 KB

    int tid  = threadIdx.x;
    int wid  = tid >> 5;    // d-group: d = 8*wid .. +8
    int lane = tid & 31;    // row within 32-row block

    float acc[8];
    #pragma unroll
    for (int t = 0; t < 8; ++t) acc[t] = 0.f;

    const float* Vb = V + (size_t)b * NSEQ * DIM;

    for (int jt = 0; jt < NSEQ; jt += 128) {
        __syncthreads();
        if (tid < 128) wt[tid] = g_w[b * NSEQ + jt + tid];
        __syncthreads();
        // Yt[j][d] = w[jt+j] * V[b][jt+j][d]
        for (int t = tid; t < 2048; t += 256) {
            int j = t >> 4, dq = t & 15;
            float4 v4 = reinterpret_cast<const float4*>(Vb + (size_t)(jt + j) * DIM)[dq];
            float wv = wt[j];
            *reinterpret_cast<float4*>(&Yt[j][dq*4]) =
                make_float4(v4.x*wv, v4.y*wv, v4.z*wv, v4.w*wv);
        }
        // S^T tile as fp32: Ssm[j*33 + r] = S[b][i0+r][jt+j]
        const __nv_bfloat16* Sb2 = g_S + ((size_t)(b * NSEQ + i0) << 10) + jt;
        for (int t = tid; t < 512; t += 256) {
            int r = t >> 4, jq = t & 15;
            uint4 v = *reinterpret_cast<const uint4*>(Sb2 + ((size_t)r << 10) + jq*8);
            Ssm[(jq*8 + 0)*33 + r] = bflo(v.x);
            Ssm[(jq*8 + 1)*33 + r] = bfhi(v.x);
            Ssm[(jq*8 + 2)*33 + r] = bflo(v.y);
            Ssm[(jq*8 + 3)*33 + r] = bfhi(v.y);
            Ssm[(jq*8 + 4)*33 + r] = bflo(v.z);
            Ssm[(jq*8 + 5)*33 + r] = bfhi(v.z);
            Ssm[(jq*8 + 6)*33 + r] = bflo(v.w);
            Ssm[(jq*8 + 7)*33 + r] = bfhi(v.w);
        }
        __syncthreads();

        #pragma unroll 8
        for (int j = 0; j < 128; ++j) {
            float s = Ssm[j*33 + lane];
            float4 y0 = *reinterpret_cast<const float4*>(&Yt[j][wid*8]);
            float4 y1 = *reinterpret_cast<const float4*>(&Yt[j][wid*8 + 4]);
            acc[0] = fmaf(s, y0.x, acc[0]); acc[1] = fmaf(s, y0.y, acc[1]);
            acc[2] = fmaf(s, y0.z, acc[2]); acc[3] = fmaf(s, y0.w, acc[3]);
            acc[4] = fmaf(s, y1.x, acc[4]); acc[5] = fmaf(s, y1.y, acc[5]);
            acc[6] = fmaf(s, y1.z, acc[6]); acc[7] = fmaf(s, y1.w, acc[7]);
        }
    }

    int row = i0 + lane;
    float a = g_a[b * NSEQ + row];
    const float* vp = Vb + (size_t)row * DIM + wid * 8;
    float* op = out + ((size_t)b * NSEQ + row) * DIM + wid * 8;
    #pragma unroll
    for (int t = 0; t < 8; ++t) op[t] = fmaf(acc[t], a, vp[t]);
}

// ---------------- launcher ----------------
extern "C" void kernel_launch(void* const* d_in, const int* in_sizes, int n_in,
                              void* d_out, int out_size) {
    const float* q = (const float*)d_in[0];
    const float* k = (const float*)d_in[1];
    const float* V = (const float*)d_in[2];
    float* out = (float*)d_out;
    (void)in_sizes; (void)n_in; (void)out_size;

    // out_kernel dynamic smem for Ssm (128*33 floats)
    cudaFuncSetAttribute(out_kernel, cudaFuncAttributeMaxDynamicSharedMemorySize,
                         128 * 33 * (int)sizeof(float));

    // choose cluster size: 16 if the HW accepts nonportable clusters, else 8
    cudaFuncSetAttribute(sink_kernel, cudaFuncAttributeNonPortableClusterSizeAllowed, 1);
    int csz = 8;
    {
        int maxC = 0;
        cudaLaunchConfig_t qcfg = {};
        qcfg.gridDim  = dim3(128);
        qcfg.blockDim = dim3(512);
        qcfg.dynamicSmemBytes = 0;
        if (cudaOccupancyMaxPotentialClusterSize(&maxC, sink_kernel, &qcfg) == cudaSuccess) {
            if (maxC >= 16) csz = 16;
        }
    }

    norm_kernel<<<2048, 256>>>(q, k);
    gemmS_kernel<<<dim3(32, 8), 256>>>();

    {
        cudaLaunchAttribute at;
        at.id = cudaLaunchAttributeClusterDimension;
        at.val.clusterDim.x = (unsigned)csz;
        at.val.clusterDim.y = 1;
        at.val.clusterDim.z = 1;
        cudaLaunchConfig_t cfg = {};
        cfg.gridDim  = dim3((unsigned)(BATCH * csz));
        cfg.blockDim = dim3(512);
        cfg.dynamicSmemBytes = 0;
        cfg.stream = 0;
        cfg.attrs = &at;
        cfg.numAttrs = 1;
        cudaLaunchKernelEx(&cfg, sink_kernel);
    }

    out_kernel<<<dim3(32, 8), 256, 128 * 33 * (int)sizeof(float)>>>(V, out);
}